// round 11
// baseline (speedup 1.0000x reference)
#include <cuda_runtime.h>
#include <cstddef>

// Wave FDTD scan: y_t = a_inv * (2/dt^2 * y_{t-1} - coef2 * y_{t-2} + c^2/h^2 * Lap(y_{t-1})),
// plus point source at (96,32). Output [B=4, T=256, 192, 192] f32.
//
// Strategy: one persistent 8-CTA cluster per batch. Each CTA owns a 24-row strip
// of the field in double-buffered SMEM. y_{t-2} and coefficients live in registers.
// Halo rows are PUSHED to neighbor CTAs via st.shared::cluster (DSMEM), so one
// barrier.cluster per timestep is the only synchronization.

#define NXg 192
#define NYg 192
#define Tg  256
#define CLUSTER 8
#define ROWS_PER 24              // 192 / 8 rows per CTA strip
#define SPLIT 2                  // threads per column (row-split)
#define ROWS_T (ROWS_PER/SPLIT)  // 12 rows per thread
#define THREADS (NYg*SPLIT)      // 384 threads

__device__ __forceinline__ unsigned mapa_u32(unsigned addr, unsigned rank) {
    unsigned ret;
    asm volatile("mapa.shared::cluster.u32 %0, %1, %2;"
                 : "=r"(ret) : "r"(addr), "r"(rank));
    return ret;
}
__device__ __forceinline__ void st_cluster_f32(unsigned addr, float v) {
    asm volatile("st.shared::cluster.f32 [%0], %1;" :: "r"(addr), "f"(v) : "memory");
}
__device__ __forceinline__ void cluster_sync_() {
    asm volatile("barrier.cluster.arrive.aligned;" ::: "memory");
    asm volatile("barrier.cluster.wait.aligned;"   ::: "memory");
}

__global__ void __launch_bounds__(THREADS, 1) __cluster_dims__(CLUSTER, 1, 1)
wave_scan_kernel(const float* __restrict__ xin,   // [B, T] source samples
                 const float* __restrict__ cin,   // [192,192] wave speed
                 const float* __restrict__ bin,   // [192,192] damping
                 float* __restrict__ out)         // [B, T, 192, 192]
{
    // Double-buffered field strip: rows 0 and ROWS_PER+1 are halo slots
    // (written by neighbor CTAs via DSMEM; stay 0 at global boundaries).
    __shared__ float sy[2][ROWS_PER + 2][NYg];
    __shared__ float xs[Tg];

    const int tid = threadIdx.x;
    const int col = tid % NYg;        // column owned by this thread
    const int hf  = tid / NYg;        // row-half (0 or 1)
    const int rk  = blockIdx.x;       // cluster rank == strip index (0..7)
    const int bt  = blockIdx.y;       // batch

    // Zero both SMEM buffers (y_{-1} = y_{-2} = 0).
    for (int r = hf; r < ROWS_PER + 2; r += SPLIT) {
        sy[0][r][col] = 0.0f;
        sy[1][r][col] = 0.0f;
    }
    // Stage this batch's source sequence in SMEM (avoids per-step LDG after
    // cluster.sync's L1D flush).
    if (tid < Tg) xs[tid] = xin[bt * Tg + tid];

    // Discretization constants (mirror reference).
    const float dtv     = 1e-3f;
    const float inv_dt2 = 1.0f / (dtv * dtv);                 // 1e6
    const float Hv      = dtv * 1.4142135623730951f * 1.01f;  // h
    const float inv_h2  = 1.0f / (Hv * Hv);

    // Per-thread rows: global rows [r0, r0 + ROWS_T)
    const int r0 = rk * ROWS_PER + hf * ROWS_T;

    float ainv[ROWS_T], cf2[ROWS_T], c2h[ROWS_T], y2[ROWS_T];
#pragma unroll
    for (int r = 0; r < ROWS_T; r++) {
        const int gi = (r0 + r) * NYg + col;
        const float bv = bin[gi];
        const float cv = cin[gi];
        const float hb = 0.5f * bv / dtv;
        ainv[r] = 1.0f / (inv_dt2 + hb);
        cf2[r]  = inv_dt2 - hb;
        c2h[r]  = cv * cv * inv_h2;   // fold 1/h^2 into c^2
        y2[r]   = 0.0f;
    }

    const bool isSrc  = (r0 == 96) && (col == 32);          // SRC_X=96 -> rk=4, hf=0, r=0
    const bool pushUp = (hf == 0)         && (rk > 0);
    const bool pushDn = (hf == SPLIT - 1) && (rk < CLUSTER - 1);

    float* oBase = out + (size_t)bt * Tg * NXg * NYg + (size_t)r0 * NYg + col;

    cluster_sync_();   // zeros + x staging visible cluster-wide

    int p = 0;
    for (int t = 0; t < Tg; t++) {
        const float xt = xs[t];
        const float (*cur)[NYg] = sy[p];
        float (*nxt)[NYg]       = sy[p ^ 1];
        float* oT = oBase + (size_t)t * (NXg * NYg);

        const int lr = hf * ROWS_T;           // SMEM row offset of this half
        float ym = cur[lr][col];              // row above first own row
        float yc = cur[lr + 1][col];          // first own row
        float first_new = 0.0f, last_new = 0.0f;

#pragma unroll
        for (int r = 0; r < ROWS_T; r++) {
            const float yp = cur[lr + r + 2][col];
            const float lf = (col > 0)       ? cur[lr + r + 1][col - 1] : 0.0f;
            const float rg = (col < NYg - 1) ? cur[lr + r + 1][col + 1] : 0.0f;
            const float lap = (ym + yp) + (lf + rg) - 4.0f * yc;
            float yn = ainv[r] * fmaf(c2h[r], lap,
                                 fmaf(-cf2[r], y2[r], (2.0f * inv_dt2) * yc));
            if (isSrc && r == 0) yn += xt;    // point source injection

            nxt[lr + r + 1][col] = yn;        // next step's y_{t-1}
            oT[(size_t)r * NYg]  = yn;        // coalesced output store

            y2[r] = yc;                       // next step's y_{t-2}
            ym = yc; yc = yp;                 // roll the vertical stencil
            if (r == 0)          first_new = yn;
            if (r == ROWS_T - 1) last_new  = yn;
        }

        // Push halo rows into neighbor CTAs' next-buffer halo slots (DSMEM).
        if (pushUp)
            st_cluster_f32(
                mapa_u32((unsigned)__cvta_generic_to_shared(&nxt[ROWS_PER + 1][col]),
                         (unsigned)(rk - 1)),
                first_new);
        if (pushDn)
            st_cluster_f32(
                mapa_u32((unsigned)__cvta_generic_to_shared(&nxt[0][col]),
                         (unsigned)(rk + 1)),
                last_new);

        p ^= 1;
        cluster_sync_();   // release our writes (incl. DSMEM), acquire neighbors'
    }
}

extern "C" void kernel_launch(void* const* d_in, const int* in_sizes, int n_in,
                              void* d_out, int out_size) {
    const float* x = (const float*)d_in[0];   // [B, T, 1]
    const float* c = (const float*)d_in[1];   // [192, 192]
    const float* b = (const float*)d_in[2];   // [192, 192]
    float* out = (float*)d_out;               // [B, T, 192, 192]

    const int B = in_sizes[0] / Tg;           // 4
    dim3 grid(CLUSTER, B, 1);                 // 4 clusters of 8 CTAs (one per batch)
    wave_scan_kernel<<<grid, THREADS>>>(x, c, b, out);
}